// round 1
// baseline (speedup 1.0000x reference)
#include <cuda_runtime.h>
#include <cuda_bf16.h>

#define B 16
#define S 200
#define D 256
#define H 8
#define W 32

// ---------------- scratch (no allocations allowed) ----------------
__device__ float g_q[B * S * D];
__device__ float g_k[B * S * D];
__device__ float g_v[B * S * D];
__device__ float g_p[(size_t)B * H * S * S];   // scores -> probs (41 MB)

// ---------------- kernel 1: fused q/k/v projection GEMM ----------------
// out[r][n] = sum_k x[r][k] * W[n][k] + b[n]   (nn.Linear: x @ W.T + b)
// Tile: 64 rows x 64 cols, K-tile 16. One shared x tile reused for 3 W's.
#define TM 64
#define TN 64
#define TK 16

__global__ __launch_bounds__(256) void proj_kernel(
    const float* __restrict__ x,
    const float* __restrict__ Wq, const float* __restrict__ bq,
    const float* __restrict__ Wk, const float* __restrict__ bk,
    const float* __restrict__ Wv, const float* __restrict__ bv)
{
    __shared__ float sx [TK][TM + 4];
    __shared__ float swq[TK][TN + 4];
    __shared__ float swk[TK][TN + 4];
    __shared__ float swv[TK][TN + 4];

    const int tx = threadIdx.x;   // 0..15
    const int ty = threadIdx.y;   // 0..15
    const int tid = ty * 16 + tx;
    const int m0 = blockIdx.x * TM;   // row block over B*S = 3200
    const int n0 = blockIdx.y * TN;   // col block over D = 256

    const int lrow = tid >> 2;         // 0..63
    const int lk   = (tid & 3) * 4;    // 0,4,8,12

    float aq[4][4] = {}, ak[4][4] = {}, av[4][4] = {};

    for (int k0 = 0; k0 < D; k0 += TK) {
        float4 vx = *(const float4*)&x [(m0 + lrow) * D + k0 + lk];
        float4 vq = *(const float4*)&Wq[(n0 + lrow) * D + k0 + lk];
        float4 vk = *(const float4*)&Wk[(n0 + lrow) * D + k0 + lk];
        float4 vv = *(const float4*)&Wv[(n0 + lrow) * D + k0 + lk];

        sx [lk + 0][lrow] = vx.x; sx [lk + 1][lrow] = vx.y;
        sx [lk + 2][lrow] = vx.z; sx [lk + 3][lrow] = vx.w;
        swq[lk + 0][lrow] = vq.x; swq[lk + 1][lrow] = vq.y;
        swq[lk + 2][lrow] = vq.z; swq[lk + 3][lrow] = vq.w;
        swk[lk + 0][lrow] = vk.x; swk[lk + 1][lrow] = vk.y;
        swk[lk + 2][lrow] = vk.z; swk[lk + 3][lrow] = vk.w;
        swv[lk + 0][lrow] = vv.x; swv[lk + 1][lrow] = vv.y;
        swv[lk + 2][lrow] = vv.z; swv[lk + 3][lrow] = vv.w;
        __syncthreads();

        #pragma unroll
        for (int kk = 0; kk < TK; kk++) {
            float xm[4], qn[4], kn[4], vn[4];
            #pragma unroll
            for (int i = 0; i < 4; i++) xm[i] = sx [kk][ty * 4 + i];
            #pragma unroll
            for (int j = 0; j < 4; j++) {
                qn[j] = swq[kk][tx * 4 + j];
                kn[j] = swk[kk][tx * 4 + j];
                vn[j] = swv[kk][tx * 4 + j];
            }
            #pragma unroll
            for (int i = 0; i < 4; i++)
                #pragma unroll
                for (int j = 0; j < 4; j++) {
                    aq[i][j] += xm[i] * qn[j];
                    ak[i][j] += xm[i] * kn[j];
                    av[i][j] += xm[i] * vn[j];
                }
        }
        __syncthreads();
    }

    #pragma unroll
    for (int i = 0; i < 4; i++) {
        int r = m0 + ty * 4 + i;
        #pragma unroll
        for (int j = 0; j < 4; j++) {
            int n = n0 + tx * 4 + j;
            g_q[r * D + n] = aq[i][j] + bq[n];
            g_k[r * D + n] = ak[i][j] + bk[n];
            g_v[r * D + n] = av[i][j] + bv[n];
        }
    }
}

// ---------------- kernel 2: scores (streams t_K, 655 MB) ----------------
// One warp per (b,i,j). score[h] = (sum_d q[i,d]*(tK[i,j,d]+k[j,d])) * rs + maskbias
__global__ __launch_bounds__(256) void scores_kernel(
    const float* __restrict__ tK, const int* __restrict__ mask)
{
    const int gw  = (blockIdx.x * blockDim.x + threadIdx.x) >> 5;
    const int lane = threadIdx.x & 31;
    if (gw >= B * S * S) return;

    const int b   = gw / (S * S);
    const int rem = gw % (S * S);
    const int i   = rem / S;
    const int j   = rem % S;

    const float* tptr = tK  + ((size_t)(b * S + i) * S + j) * D;
    const float* qptr = g_q + (size_t)(b * S + i) * D;
    const float* kptr = g_k + (size_t)(b * S + j) * D;

    const int off = lane * 8;
    float4 t0 = *(const float4*)(tptr + off);
    float4 t1 = *(const float4*)(tptr + off + 4);
    float4 q0 = *(const float4*)(qptr + off);
    float4 q1 = *(const float4*)(qptr + off + 4);
    float4 k0 = *(const float4*)(kptr + off);
    float4 k1 = *(const float4*)(kptr + off + 4);

    float p = q0.x * (t0.x + k0.x) + q0.y * (t0.y + k0.y)
            + q0.z * (t0.z + k0.z) + q0.w * (t0.w + k0.w)
            + q1.x * (t1.x + k1.x) + q1.y * (t1.y + k1.y)
            + q1.z * (t1.z + k1.z) + q1.w * (t1.w + k1.w);

    // reduce within each 4-lane group (one head per group)
    p += __shfl_xor_sync(0xFFFFFFFFu, p, 1);
    p += __shfl_xor_sync(0xFFFFFFFFu, p, 2);

    if ((lane & 3) == 0) {
        const int h = lane >> 2;
        const float mb = 10000.0f * (1.0f - (float)mask[b * S + j]);
        const float sc = p * 0.17677669529663689f + mb;  // 1/sqrt(32)
        g_p[(((size_t)b * H + h) * S + i) * S + j] = sc;
    }
}

// ---------------- kernel 3: softmax over j, warp per row ----------------
__global__ __launch_bounds__(256) void softmax_kernel()
{
    const int row  = (blockIdx.x * blockDim.x + threadIdx.x) >> 5;
    const int lane = threadIdx.x & 31;
    if (row >= B * H * S) return;

    float* p = g_p + (size_t)row * S;

    float vals[7];
    float mx = -1e30f;
    #pragma unroll
    for (int t = 0; t < 7; t++) {
        int j = lane + t * 32;
        vals[t] = (j < S) ? p[j] : -1e30f;
        mx = fmaxf(mx, vals[t]);
    }
    #pragma unroll
    for (int o = 16; o; o >>= 1) mx = fmaxf(mx, __shfl_xor_sync(0xFFFFFFFFu, mx, o));

    float sum = 0.f;
    #pragma unroll
    for (int t = 0; t < 7; t++) {
        vals[t] = __expf(vals[t] - mx);   // exp(-huge) == 0 for padded lanes
        sum += vals[t];
    }
    #pragma unroll
    for (int o = 16; o; o >>= 1) sum += __shfl_xor_sync(0xFFFFFFFFu, sum, o);

    const float inv = 1.0f / sum;
    #pragma unroll
    for (int t = 0; t < 7; t++) {
        int j = lane + t * 32;
        if (j < S) p[j] = vals[t] * inv;
    }
}

// ---------------- kernel 4: output (streams t_V, 655 MB) ----------------
// Block per (b,i), thread per d. out[d] = sum_j p[h,i,j] * (tV[i,j,d] + v[j,d])
__global__ __launch_bounds__(256) void out_kernel(
    const float* __restrict__ tV, float* __restrict__ out)
{
    __shared__ float sp[H * S];   // 1600 floats = 6.4 KB

    const int bi = blockIdx.x;        // 0 .. B*S-1
    const int b  = bi / S;
    const int i  = bi % S;
    const int d  = threadIdx.x;       // 0..255

    for (int idx = d; idx < H * S; idx += 256) {
        const int h = idx / S, j = idx % S;
        sp[idx] = g_p[(((size_t)b * H + h) * S + i) * S + j];
    }
    __syncthreads();

    const int h = d >> 5;
    const float* tptr = tV  + (size_t)bi * S * D + d;
    const float* vptr = g_v + (size_t)b * S * D + d;
    const float* ph   = sp + h * S;

    float acc = 0.f;
    #pragma unroll 4
    for (int j = 0; j < S; j++) {
        acc += ph[j] * (tptr[(size_t)j * D] + vptr[(size_t)j * D]);
    }
    out[(size_t)bi * D + d] = acc;
}

// ---------------- launch ----------------
extern "C" void kernel_launch(void* const* d_in, const int* in_sizes, int n_in,
                              void* d_out, int out_size)
{
    const float* x    = (const float*)d_in[0];
    const float* tK   = (const float*)d_in[1];
    const float* tV   = (const float*)d_in[2];
    const int*   mask = (const int*)  d_in[3];
    const float* Wq   = (const float*)d_in[4];
    const float* bq   = (const float*)d_in[5];
    const float* Wk   = (const float*)d_in[6];
    const float* bk   = (const float*)d_in[7];
    const float* Wv   = (const float*)d_in[8];
    const float* bv   = (const float*)d_in[9];
    float* out = (float*)d_out;

    // 1) projections: grid (3200/64, 256/64)
    dim3 pgrid(B * S / TM, D / TN);
    dim3 pblk(16, 16);
    proj_kernel<<<pgrid, pblk>>>(x, Wq, bq, Wk, bk, Wv, bv);

    // 2) scores: one warp per (b,i,j) -> B*S*S warps, 8 warps/block
    {
        int nwarps = B * S * S;
        int nblk = (nwarps + 7) / 8;
        scores_kernel<<<nblk, 256>>>(tK, mask);
    }

    // 3) softmax: one warp per (b,h,i) row
    {
        int nrows = B * H * S;
        int nblk = (nrows + 7) / 8;
        softmax_kernel<<<nblk, 256>>>();
    }

    // 4) output: block per (b,i)
    out_kernel<<<B * S, 256>>>(tV, out);
}

// round 2
// speedup vs baseline: 1.2338x; 1.2338x over previous
#include <cuda_runtime.h>
#include <cuda_bf16.h>

#define B 16
#define S 200
#define D 256
#define H 8
#define W 32
#define RS 0.17677669529663689f   // 1/sqrt(32)

// ---------------- scratch (no allocations allowed) ----------------
__device__ float g_q[B * S * D];
__device__ float g_k[B * S * D];
__device__ float g_v[B * S * D];

// ---------------- kernel 1: fused q/k/v projection GEMM ----------------
#define TM 64
#define TN 64
#define TK 16

__global__ __launch_bounds__(256) void proj_kernel(
    const float* __restrict__ x,
    const float* __restrict__ Wq, const float* __restrict__ bq,
    const float* __restrict__ Wk, const float* __restrict__ bk,
    const float* __restrict__ Wv, const float* __restrict__ bv)
{
    __shared__ float sx [TK][TM + 4];
    __shared__ float swq[TK][TN + 4];
    __shared__ float swk[TK][TN + 4];
    __shared__ float swv[TK][TN + 4];

    const int tx = threadIdx.x;   // 0..15
    const int ty = threadIdx.y;   // 0..15
    const int tid = ty * 16 + tx;
    const int m0 = blockIdx.x * TM;
    const int n0 = blockIdx.y * TN;

    const int lrow = tid >> 2;
    const int lk   = (tid & 3) * 4;

    float aq[4][4] = {}, ak[4][4] = {}, av[4][4] = {};

    for (int k0 = 0; k0 < D; k0 += TK) {
        float4 vx = *(const float4*)&x [(m0 + lrow) * D + k0 + lk];
        float4 vq = *(const float4*)&Wq[(n0 + lrow) * D + k0 + lk];
        float4 vk = *(const float4*)&Wk[(n0 + lrow) * D + k0 + lk];
        float4 vv = *(const float4*)&Wv[(n0 + lrow) * D + k0 + lk];

        sx [lk + 0][lrow] = vx.x; sx [lk + 1][lrow] = vx.y;
        sx [lk + 2][lrow] = vx.z; sx [lk + 3][lrow] = vx.w;
        swq[lk + 0][lrow] = vq.x; swq[lk + 1][lrow] = vq.y;
        swq[lk + 2][lrow] = vq.z; swq[lk + 3][lrow] = vq.w;
        swk[lk + 0][lrow] = vk.x; swk[lk + 1][lrow] = vk.y;
        swk[lk + 2][lrow] = vk.z; swk[lk + 3][lrow] = vk.w;
        swv[lk + 0][lrow] = vv.x; swv[lk + 1][lrow] = vv.y;
        swv[lk + 2][lrow] = vv.z; swv[lk + 3][lrow] = vv.w;
        __syncthreads();

        #pragma unroll
        for (int kk = 0; kk < TK; kk++) {
            float xm[4], qn[4], kn[4], vn[4];
            #pragma unroll
            for (int i = 0; i < 4; i++) xm[i] = sx [kk][ty * 4 + i];
            #pragma unroll
            for (int j = 0; j < 4; j++) {
                qn[j] = swq[kk][tx * 4 + j];
                kn[j] = swk[kk][tx * 4 + j];
                vn[j] = swv[kk][tx * 4 + j];
            }
            #pragma unroll
            for (int i = 0; i < 4; i++)
                #pragma unroll
                for (int j = 0; j < 4; j++) {
                    aq[i][j] += xm[i] * qn[j];
                    ak[i][j] += xm[i] * kn[j];
                    av[i][j] += xm[i] * vn[j];
                }
        }
        __syncthreads();
    }

    #pragma unroll
    for (int i = 0; i < 4; i++) {
        int r = m0 + ty * 4 + i;
        #pragma unroll
        for (int j = 0; j < 4; j++) {
            int n = n0 + tx * 4 + j;
            g_q[r * D + n] = aq[i][j] + bq[n];
            g_k[r * D + n] = ak[i][j] + bk[n];
            g_v[r * D + n] = av[i][j] + bv[n];
        }
    }
}

// ---------------- kernel 2: fully fused attention, block per (b,i) ----------------
// Phase A: scores[h][j] = sum_d q[i,d]*(tK[i,j,d]+k[j,d])  (8 warps x 25 j)
// Phase B: per-head softmax with scale + mask bias (warp per head)
// Phase C: out[d] = sum_j p[h(d)][j]*(tV[i,j,d]+v[j,d])    (4 j-groups x 64 d-slices)
__global__ __launch_bounds__(256) void fused_attn_kernel(
    const float* __restrict__ tK, const float* __restrict__ tV,
    const int* __restrict__ mask, float* __restrict__ out)
{
    __shared__ float sp[H][S];          // scores -> probs, 6.4 KB
    __shared__ float4 pbuf[4][64];      // phase-C partials, 4 KB

    const int bi = blockIdx.x;          // 0..B*S-1
    const int b  = bi / S;
    const int i  = bi % S;
    const int warp = threadIdx.x >> 5;  // 0..7
    const int lane = threadIdx.x & 31;

    // ---- Phase A: scores ----
    {
        const float* qrow = g_q + (size_t)bi * D + lane * 8;
        const float4 qa = *(const float4*)(qrow);
        const float4 qb = *(const float4*)(qrow + 4);

        #pragma unroll 5
        for (int j = warp; j < S; j += 8) {
            const float* tp = tK  + ((size_t)bi * S + j) * D + lane * 8;
            const float* kp = g_k + ((size_t)(b * S + j)) * D + lane * 8;
            float4 t0 = *(const float4*)(tp);
            float4 t1 = *(const float4*)(tp + 4);
            float4 k0 = *(const float4*)(kp);
            float4 k1 = *(const float4*)(kp + 4);

            float p = qa.x * (t0.x + k0.x) + qa.y * (t0.y + k0.y)
                    + qa.z * (t0.z + k0.z) + qa.w * (t0.w + k0.w)
                    + qb.x * (t1.x + k1.x) + qb.y * (t1.y + k1.y)
                    + qb.z * (t1.z + k1.z) + qb.w * (t1.w + k1.w);

            p += __shfl_xor_sync(0xFFFFFFFFu, p, 1);
            p += __shfl_xor_sync(0xFFFFFFFFu, p, 2);
            if ((lane & 3) == 0) sp[lane >> 2][j] = p;
        }
    }
    __syncthreads();

    // ---- Phase B: softmax (warp h handles head h) ----
    {
        float vals[7];
        float mx = -1e30f;
        #pragma unroll
        for (int t = 0; t < 7; t++) {
            int j = lane + t * 32;
            if (j < S) {
                float mb = 10000.0f * (1.0f - (float)mask[b * S + j]);
                vals[t] = sp[warp][j] * RS + mb;
            } else {
                vals[t] = -1e30f;
            }
            mx = fmaxf(mx, vals[t]);
        }
        #pragma unroll
        for (int o = 16; o; o >>= 1) mx = fmaxf(mx, __shfl_xor_sync(0xFFFFFFFFu, mx, o));

        float sum = 0.f;
        #pragma unroll
        for (int t = 0; t < 7; t++) {
            vals[t] = __expf(vals[t] - mx);
            sum += vals[t];
        }
        #pragma unroll
        for (int o = 16; o; o >>= 1) sum += __shfl_xor_sync(0xFFFFFFFFu, sum, o);

        const float inv = 1.0f / sum;
        #pragma unroll
        for (int t = 0; t < 7; t++) {
            int j = lane + t * 32;
            if (j < S) sp[warp][j] = vals[t] * inv;
        }
    }
    __syncthreads();

    // ---- Phase C: output ----
    {
        const int g = threadIdx.x >> 6;     // j-group 0..3
        const int l = threadIdx.x & 63;     // d-slice 0..63
        const int d = l * 4;
        const int h = l >> 3;               // head of this d-slice

        const float* tvb = tV  + ((size_t)bi * S) * D + d;
        const float* vvb = g_v + ((size_t)b * S) * D + d;

        float4 acc = make_float4(0.f, 0.f, 0.f, 0.f);
        #pragma unroll 5
        for (int j = g; j < S; j += 4) {
            float4 tv = *(const float4*)(tvb + (size_t)j * D);
            float4 vv = *(const float4*)(vvb + (size_t)j * D);
            float pj = sp[h][j];
            acc.x += pj * (tv.x + vv.x);
            acc.y += pj * (tv.y + vv.y);
            acc.z += pj * (tv.z + vv.z);
            acc.w += pj * (tv.w + vv.w);
        }
        pbuf[g][l] = acc;
    }
    __syncthreads();

    if (threadIdx.x < 64) {
        const int l = threadIdx.x;
        float4 a0 = pbuf[0][l], a1 = pbuf[1][l], a2 = pbuf[2][l], a3 = pbuf[3][l];
        float4 r;
        r.x = (a0.x + a1.x) + (a2.x + a3.x);
        r.y = (a0.y + a1.y) + (a2.y + a3.y);
        r.z = (a0.z + a1.z) + (a2.z + a3.z);
        r.w = (a0.w + a1.w) + (a2.w + a3.w);
        *(float4*)(out + (size_t)bi * D + l * 4) = r;
    }
}

// ---------------- launch ----------------
extern "C" void kernel_launch(void* const* d_in, const int* in_sizes, int n_in,
                              void* d_out, int out_size)
{
    const float* x    = (const float*)d_in[0];
    const float* tK   = (const float*)d_in[1];
    const float* tV   = (const float*)d_in[2];
    const int*   mask = (const int*)  d_in[3];
    const float* Wq   = (const float*)d_in[4];
    const float* bq   = (const float*)d_in[5];
    const float* Wk   = (const float*)d_in[6];
    const float* bk   = (const float*)d_in[7];
    const float* Wv   = (const float*)d_in[8];
    const float* bv   = (const float*)d_in[9];
    float* out = (float*)d_out;

    dim3 pgrid(B * S / TM, D / TN);
    dim3 pblk(16, 16);
    proj_kernel<<<pgrid, pblk>>>(x, Wq, bq, Wk, bk, Wv, bv);

    fused_attn_kernel<<<B * S, 256>>>(tK, tV, mask, out);
}

// round 3
// speedup vs baseline: 1.2758x; 1.0340x over previous
#include <cuda_runtime.h>
#include <cuda_bf16.h>

#define B 16
#define S 200
#define D 256
#define H 8
#define W 32
#define RS 0.17677669529663689f   // 1/sqrt(32)

// ---------------- scratch (no allocations allowed) ----------------
__device__ float g_q[B * S * D];
__device__ float g_k[B * S * D];
__device__ float g_v[B * S * D];

// ---------------- kernel 1: fused q/k/v projection GEMM ----------------
// 32x64 output tile per block -> 400 blocks (was 200), 2x4 register tile.
#define TM 32
#define TN 64
#define TK 16

__global__ __launch_bounds__(256) void proj_kernel(
    const float* __restrict__ x,
    const float* __restrict__ Wq, const float* __restrict__ bq,
    const float* __restrict__ Wk, const float* __restrict__ bk,
    const float* __restrict__ Wv, const float* __restrict__ bv)
{
    __shared__ float sx [TK][TM + 4];
    __shared__ float swq[TK][TN + 4];
    __shared__ float swk[TK][TN + 4];
    __shared__ float swv[TK][TN + 4];

    const int tid = threadIdx.x;
    const int tx = tid & 15;        // col group (4 cols each)
    const int ty = tid >> 4;        // row group (2 rows each)
    const int m0 = blockIdx.x * TM;
    const int n0 = blockIdx.y * TN;

    const int wrow = tid >> 2;          // 0..63 for W tiles
    const int wk   = (tid & 3) * 4;
    const int xrow = tid >> 3;          // 0..31 for x tile
    const int xk   = (tid & 7) * 2;

    float aq[2][4] = {}, ak[2][4] = {}, av[2][4] = {};

    for (int k0 = 0; k0 < D; k0 += TK) {
        float2 vx = *(const float2*)&x [(m0 + xrow) * D + k0 + xk];
        float4 vq = *(const float4*)&Wq[(n0 + wrow) * D + k0 + wk];
        float4 vk = *(const float4*)&Wk[(n0 + wrow) * D + k0 + wk];
        float4 vv = *(const float4*)&Wv[(n0 + wrow) * D + k0 + wk];

        sx [xk + 0][xrow] = vx.x; sx [xk + 1][xrow] = vx.y;
        swq[wk + 0][wrow] = vq.x; swq[wk + 1][wrow] = vq.y;
        swq[wk + 2][wrow] = vq.z; swq[wk + 3][wrow] = vq.w;
        swk[wk + 0][wrow] = vk.x; swk[wk + 1][wrow] = vk.y;
        swk[wk + 2][wrow] = vk.z; swk[wk + 3][wrow] = vk.w;
        swv[wk + 0][wrow] = vv.x; swv[wk + 1][wrow] = vv.y;
        swv[wk + 2][wrow] = vv.z; swv[wk + 3][wrow] = vv.w;
        __syncthreads();

        #pragma unroll
        for (int kk = 0; kk < TK; kk++) {
            float xm[2], qn[4], kn[4], vn[4];
            #pragma unroll
            for (int i = 0; i < 2; i++) xm[i] = sx[kk][ty * 2 + i];
            #pragma unroll
            for (int j = 0; j < 4; j++) {
                qn[j] = swq[kk][tx * 4 + j];
                kn[j] = swk[kk][tx * 4 + j];
                vn[j] = swv[kk][tx * 4 + j];
            }
            #pragma unroll
            for (int i = 0; i < 2; i++)
                #pragma unroll
                for (int j = 0; j < 4; j++) {
                    aq[i][j] += xm[i] * qn[j];
                    ak[i][j] += xm[i] * kn[j];
                    av[i][j] += xm[i] * vn[j];
                }
        }
        __syncthreads();
    }

    #pragma unroll
    for (int i = 0; i < 2; i++) {
        int r = m0 + ty * 2 + i;
        #pragma unroll
        for (int j = 0; j < 4; j++) {
            int n = n0 + tx * 4 + j;
            g_q[r * D + n] = aq[i][j] + bq[n];
            g_k[r * D + n] = ak[i][j] + bk[n];
            g_v[r * D + n] = av[i][j] + bv[n];
        }
    }
}

// ---------------- kernel 2: fully fused attention, block per (b,i) ----------------
__global__ __launch_bounds__(256, 6) void fused_attn_kernel(
    const float* __restrict__ tK, const float* __restrict__ tV,
    const int* __restrict__ mask, float* __restrict__ out)
{
    __shared__ float sp[H][S];          // scores -> probs, 6.4 KB
    __shared__ float4 pbuf[4][64];      // phase-C partials, 4 KB

    const int bi = blockIdx.x;          // 0..B*S-1
    const int b  = bi / S;
    const int warp = threadIdx.x >> 5;  // 0..7
    const int lane = threadIdx.x & 31;

    // ---- Phase A: scores[h][j] = sum_d q[i,d]*(tK[i,j,d]+k[j,d]) ----
    {
        const float* qrow = g_q + (size_t)bi * D + lane * 8;
        const float4 qa = *(const float4*)(qrow);
        const float4 qb = *(const float4*)(qrow + 4);

        #pragma unroll 5
        for (int j = warp; j < S; j += 8) {
            const float* tp = tK  + ((size_t)bi * S + j) * D + lane * 8;
            const float* kp = g_k + ((size_t)(b * S + j)) * D + lane * 8;
            float4 t0 = __ldcs((const float4*)(tp));        // streaming: no reuse
            float4 t1 = __ldcs((const float4*)(tp + 4));
            float4 k0 = *(const float4*)(kp);
            float4 k1 = *(const float4*)(kp + 4);

            float p = qa.x * (t0.x + k0.x) + qa.y * (t0.y + k0.y)
                    + qa.z * (t0.z + k0.z) + qa.w * (t0.w + k0.w)
                    + qb.x * (t1.x + k1.x) + qb.y * (t1.y + k1.y)
                    + qb.z * (t1.z + k1.z) + qb.w * (t1.w + k1.w);

            p += __shfl_xor_sync(0xFFFFFFFFu, p, 1);
            p += __shfl_xor_sync(0xFFFFFFFFu, p, 2);
            if ((lane & 3) == 0) sp[lane >> 2][j] = p;
        }
    }
    __syncthreads();

    // ---- Phase B: per-head softmax (warp h handles head h) ----
    {
        float vals[7];
        float mx = -1e30f;
        #pragma unroll
        for (int t = 0; t < 7; t++) {
            int j = lane + t * 32;
            if (j < S) {
                float mb = 10000.0f * (1.0f - (float)mask[b * S + j]);
                vals[t] = sp[warp][j] * RS + mb;
            } else {
                vals[t] = -1e30f;
            }
            mx = fmaxf(mx, vals[t]);
        }
        #pragma unroll
        for (int o = 16; o; o >>= 1) mx = fmaxf(mx, __shfl_xor_sync(0xFFFFFFFFu, mx, o));

        float sum = 0.f;
        #pragma unroll
        for (int t = 0; t < 7; t++) {
            vals[t] = __expf(vals[t] - mx);
            sum += vals[t];
        }
        #pragma unroll
        for (int o = 16; o; o >>= 1) sum += __shfl_xor_sync(0xFFFFFFFFu, sum, o);

        const float inv = 1.0f / sum;
        #pragma unroll
        for (int t = 0; t < 7; t++) {
            int j = lane + t * 32;
            if (j < S) sp[warp][j] = vals[t] * inv;
        }
    }
    __syncthreads();

    // ---- Phase C: out[d] = sum_j p[h(d)][j]*(tV[i,j,d]+v[j,d]) ----
    {
        const int g = threadIdx.x >> 6;     // j-group 0..3
        const int l = threadIdx.x & 63;     // d-slice 0..63
        const int d = l * 4;
        const int h = l >> 3;

        const float* tvb = tV  + ((size_t)bi * S) * D + d;
        const float* vvb = g_v + ((size_t)b * S) * D + d;

        float4 acc = make_float4(0.f, 0.f, 0.f, 0.f);
        #pragma unroll 5
        for (int j = g; j < S; j += 4) {
            float4 tv = __ldcs((const float4*)(tvb + (size_t)j * D));
            float4 vv = *(const float4*)(vvb + (size_t)j * D);
            float pj = sp[h][j];
            acc.x += pj * (tv.x + vv.x);
            acc.y += pj * (tv.y + vv.y);
            acc.z += pj * (tv.z + vv.z);
            acc.w += pj * (tv.w + vv.w);
        }
        pbuf[g][l] = acc;
    }
    __syncthreads();

    if (threadIdx.x < 64) {
        const int l = threadIdx.x;
        float4 a0 = pbuf[0][l], a1 = pbuf[1][l], a2 = pbuf[2][l], a3 = pbuf[3][l];
        float4 r;
        r.x = (a0.x + a1.x) + (a2.x + a3.x);
        r.y = (a0.y + a1.y) + (a2.y + a3.y);
        r.z = (a0.z + a1.z) + (a2.z + a3.z);
        r.w = (a0.w + a1.w) + (a2.w + a3.w);
        *(float4*)(out + (size_t)bi * D + l * 4) = r;
    }
}

// ---------------- launch ----------------
extern "C" void kernel_launch(void* const* d_in, const int* in_sizes, int n_in,
                              void* d_out, int out_size)
{
    const float* x    = (const float*)d_in[0];
    const float* tK   = (const float*)d_in[1];
    const float* tV   = (const float*)d_in[2];
    const int*   mask = (const int*)  d_in[3];
    const float* Wq   = (const float*)d_in[4];
    const float* bq   = (const float*)d_in[5];
    const float* Wk   = (const float*)d_in[6];
    const float* bk   = (const float*)d_in[7];
    const float* Wv   = (const float*)d_in[8];
    const float* bv   = (const float*)d_in[9];
    float* out = (float*)d_out;

    dim3 pgrid(B * S / TM, D / TN);   // (100, 4) = 400 blocks
    proj_kernel<<<pgrid, 256>>>(x, Wq, bq, Wk, bk, Wv, bv);

    fused_attn_kernel<<<B * S, 256>>>(tK, tV, mask, out);
}